// round 6
// baseline (speedup 1.0000x reference)
#include <cuda_runtime.h>
#include <math.h>

#define F_N 16384
#define H_N 64
#define TH  192   // 3*H

// Scratch (no allocations allowed): mask count + masked-sum accumulator.
__device__ int    g_count;
__device__ double g_agg[H_N];

// Accurate tanh via expf identity (immune to fast-math MUFU.TANH lowering).
__device__ __forceinline__ float tanh_acc(float x) {
    float ax = fabsf(x);
    float e  = expf(-2.0f * ax);          // in (0,1], no overflow
    float t  = (1.0f - e) / (1.0f + e);
    return copysignf(t, x);
}

// ---------------------------------------------------------------------------
// k0: count mask (denom + the jnp.any(mask) branch), zero agg accumulator.
// mask arrives as int32 (harness converts bool -> int32; only f32/i32/bf16 exist).
// ---------------------------------------------------------------------------
__global__ void k0_mask(const int* __restrict__ mask) {
    __shared__ int s[256];
    int t = threadIdx.x;
    int c = 0;
    #pragma unroll 4
    for (int i = t; i < F_N; i += 256) c += (mask[i] != 0);
    s[t] = c;
    __syncthreads();
    for (int off = 128; off; off >>= 1) {
        if (t < off) s[t] += s[t + off];
        __syncthreads();
    }
    if (t == 0) g_count = s[0];
    if (t < H_N) g_agg[t] = 0.0;
}

// ---------------------------------------------------------------------------
// k1: per-feature GRU cell. One block per feature, 256 threads.
//     Streams the 48KB U_w[f] slab as float4 (fully coalesced), computes
//     U_T[192] via width-16 shuffle reduction, then 64 threads do the gates
//     and write H_curr.
// ---------------------------------------------------------------------------
__global__ void __launch_bounds__(256, 8)
k1_gru(const float* __restrict__ X,
       const int* __restrict__ mask,
       const float* __restrict__ Ht,
       const float* __restrict__ xTw,
       const float* __restrict__ xTb,
       const float* __restrict__ Uw,
       float* __restrict__ out) {
    const int f = blockIdx.x;
    const int t = threadIdx.x;

    __shared__ float Ht_s[H_N];
    __shared__ float uT[TH];

    if (t < H_N) Ht_s[t] = Ht[(size_t)f * H_N + t];
    __syncthreads();

    // vec index v = t + 256*it -> float pos p = 4v. p & 63 = (4t) & 63
    // (1024 % 64 == 0), i = p >> 6 = (t >> 4) + 16*it.
    // So thread t always multiplies the same 4 Ht values; 16 consecutive
    // threads share an output row i.
    const int s16 = t & 15;
    const float4 hv = *reinterpret_cast<const float4*>(&Ht_s[s16 * 4]);

    const float4* __restrict__ Uv =
        reinterpret_cast<const float4*>(Uw + (size_t)f * (TH * H_N));

    float acc[12];
    #pragma unroll
    for (int it = 0; it < 12; it++) {
        float4 w = Uv[t + 256 * it];
        acc[it] = fmaf(w.x, hv.x, fmaf(w.y, hv.y, fmaf(w.z, hv.z, w.w * hv.w)));
    }

    #pragma unroll
    for (int it = 0; it < 12; it++) {
        float v = acc[it];
        v += __shfl_down_sync(0xffffffffu, v, 8, 16);
        v += __shfl_down_sync(0xffffffffu, v, 4, 16);
        v += __shfl_down_sync(0xffffffffu, v, 2, 16);
        v += __shfl_down_sync(0xffffffffu, v, 1, 16);
        if (s16 == 0) uT[(t >> 4) + 16 * it] = v;
    }
    __syncthreads();

    if (t < H_N) {
        const size_t base = (size_t)f * TH;
        const float Xf = X[f];
        float xz = fmaf(xTw[base + t],           Xf, xTb[base + t]);
        float xr = fmaf(xTw[base + H_N + t],     Xf, xTb[base + H_N + t]);
        float xh = fmaf(xTw[base + 2 * H_N + t], Xf, xTb[base + 2 * H_N + t]);

        float z  = 1.0f / (1.0f + expf(-(xz + uT[t])));
        float r  = 1.0f / (1.0f + expf(-(xr + uT[H_N + t])));
        float ht = tanh_acc(fmaf(r, uT[2 * H_N + t], xh));
        float hg = z * Ht_s[t] + (1.0f - z) * ht;   // match reference form

        float oh;
        if (g_count > 0) oh = (mask[f] != 0) ? hg : 0.0f;
        else             oh = Ht_s[t];              // jnp.any(mask) == False

        // out layout: [pred(2), H_curr(F*H)]
        out[2 + (size_t)f * H_N + t] = oh;
    }
}

// ---------------------------------------------------------------------------
// k2: agg[h] = sum_f mask[f] * H_curr[f][h]  (== sum(h_gate*mask) in all
//     branches). H_curr (4MB) is L2-resident after k1. Double accumulation.
// ---------------------------------------------------------------------------
__global__ void k2_agg(const int* __restrict__ mask,
                       const float* __restrict__ out) {
    __shared__ double s[256];
    const int t = threadIdx.x;
    const int h  = t & 63;
    const int fl = t >> 6;              // 0..3
    const int base = blockIdx.x * 128;  // 128 features per block

    double acc = 0.0;
    #pragma unroll 4
    for (int i = 0; i < 32; i++) {
        int f = base + fl + 4 * i;
        if (mask[f] != 0)
            acc += (double)out[2 + (size_t)f * H_N + h];
    }
    s[t] = acc;
    __syncthreads();
    if (t < 64) {
        double v = s[t] + s[t + 64] + s[t + 128] + s[t + 192];
        atomicAdd(&g_agg[t], v);
    }
}

// ---------------------------------------------------------------------------
// k3: tiny MLP head + 2-class softmax. One block, 64 threads, double math.
// ---------------------------------------------------------------------------
__global__ void k3_mlp(const float* __restrict__ W1, const float* __restrict__ b1,
                       const float* __restrict__ W2, const float* __restrict__ b2,
                       float* __restrict__ out) {
    __shared__ double s_agg[H_N];
    __shared__ double s_hid[H_N];
    __shared__ double s_log[2];
    const int t = threadIdx.x;

    const double denom = fmax((double)g_count, 1.0);
    if (t < H_N) s_agg[t] = g_agg[t] / denom;
    __syncthreads();

    if (t < H_N) {
        double a = (double)b1[t];
        for (int h = 0; h < H_N; h++) a += s_agg[h] * (double)W1[h * H_N + t];
        s_hid[t] = fmax(a, 0.0);
    }
    __syncthreads();

    if (t < 2) {
        double a = (double)b2[t];
        for (int j = 0; j < H_N; j++) a += s_hid[j] * (double)W2[j * 2 + t];
        s_log[t] = a;
    }
    __syncthreads();

    if (t < 2) {
        double m  = fmax(s_log[0], s_log[1]);
        double e0 = exp(s_log[0] - m);
        double e1 = exp(s_log[1] - m);
        out[t] = (float)(((t == 0) ? e0 : e1) / (e0 + e1));
    }
}

// ---------------------------------------------------------------------------
// Inputs (metadata order): 0:tim(i32) 1:X 2:X_hap 3:mask(i32!) 4:Ht 5:xT_w
//                          6:xT_b 7:U_w 8:W1 9:b1 10:W2 11:b2
// Output: [pred(2), H_curr(16384*64)] float32
// ---------------------------------------------------------------------------
extern "C" void kernel_launch(void* const* d_in, const int* in_sizes, int n_in,
                              void* d_out, int out_size) {
    const float* X    = (const float*)d_in[1];
    const int*   mask = (const int*)d_in[3];     // bool -> int32 in harness
    const float* Ht   = (const float*)d_in[4];
    const float* xTw  = (const float*)d_in[5];
    const float* xTb  = (const float*)d_in[6];
    const float* Uw   = (const float*)d_in[7];
    const float* W1   = (const float*)d_in[8];
    const float* b1   = (const float*)d_in[9];
    const float* W2   = (const float*)d_in[10];
    const float* b2   = (const float*)d_in[11];
    float* out = (float*)d_out;

    k0_mask<<<1, 256>>>(mask);
    k1_gru<<<F_N, 256>>>(X, mask, Ht, xTw, xTb, Uw, out);
    k2_agg<<<F_N / 128, 256>>>(mask, out);
    k3_mlp<<<1, 64>>>(W1, b1, W2, b2, out);
}

// round 10
// speedup vs baseline: 1.0982x; 1.0982x over previous
#include <cuda_runtime.h>
#include <math.h>

#define F_N 16384
#define H_N 64
#define TH  192   // 3*H

// Scratch (no allocations allowed): mask count + masked-sum accumulator.
__device__ int    g_count;
__device__ double g_agg[H_N];

// Accurate tanh via expf identity (immune to fast-math MUFU.TANH lowering).
__device__ __forceinline__ float tanh_acc(float x) {
    float ax = fabsf(x);
    float e  = expf(-2.0f * ax);          // in (0,1], no overflow
    float t  = (1.0f - e) / (1.0f + e);
    return copysignf(t, x);
}

// ---------------------------------------------------------------------------
// k0: count mask (denom + the jnp.any(mask) branch), zero agg accumulator.
// mask arrives as int32 (harness ships bool as int32).
// ---------------------------------------------------------------------------
__global__ void k0_mask(const int* __restrict__ mask) {
    __shared__ int s[256];
    int t = threadIdx.x;
    const int4* m4 = (const int4*)mask;
    int c = 0;
    #pragma unroll 4
    for (int i = t; i < F_N / 4; i += 256) {
        int4 v = m4[i];
        c += (v.x != 0) + (v.y != 0) + (v.z != 0) + (v.w != 0);
    }
    s[t] = c;
    __syncthreads();
    for (int off = 128; off; off >>= 1) {
        if (t < off) s[t] += s[t + off];
        __syncthreads();
    }
    if (t == 0) g_count = s[0];
    if (t < H_N) g_agg[t] = 0.0;
}

// ---------------------------------------------------------------------------
// k1: per-feature GRU cell. One block per feature, 256 threads.
//     Streams the 48KB U_w[f] slab as float4 (fully coalesced), computes
//     U_T[192] via width-16 shuffle reduction, then 64 threads do the gates
//     and write H_curr. No occupancy cap: 12 in-flight LDG.128 need ~56 regs;
//     a 32-reg cap (occ 8) would spill / throttle MLP.
// ---------------------------------------------------------------------------
__global__ void __launch_bounds__(256)
k1_gru(const float* __restrict__ X,
       const int* __restrict__ mask,
       const float* __restrict__ Ht,
       const float* __restrict__ xTw,
       const float* __restrict__ xTb,
       const float* __restrict__ Uw,
       float* __restrict__ out) {
    const int f = blockIdx.x;
    const int t = threadIdx.x;

    __shared__ float Ht_s[H_N];
    __shared__ float uT[TH];

    if (t < H_N) Ht_s[t] = Ht[(size_t)f * H_N + t];
    __syncthreads();

    // vec index v = t + 256*it -> float pos p = 4v. p & 63 = (4t) & 63
    // (1024 % 64 == 0), i = p >> 6 = (t >> 4) + 16*it.
    // Thread t always multiplies the same 4 Ht values; 16 consecutive
    // threads share an output row i.
    const int s16 = t & 15;
    const float4 hv = *reinterpret_cast<const float4*>(&Ht_s[s16 * 4]);

    const float4* __restrict__ Uv =
        reinterpret_cast<const float4*>(Uw + (size_t)f * (TH * H_N));

    float acc[12];
    #pragma unroll
    for (int it = 0; it < 12; it++) {
        float4 w = Uv[t + 256 * it];
        acc[it] = fmaf(w.x, hv.x, fmaf(w.y, hv.y, fmaf(w.z, hv.z, w.w * hv.w)));
    }

    #pragma unroll
    for (int it = 0; it < 12; it++) {
        float v = acc[it];
        v += __shfl_down_sync(0xffffffffu, v, 8, 16);
        v += __shfl_down_sync(0xffffffffu, v, 4, 16);
        v += __shfl_down_sync(0xffffffffu, v, 2, 16);
        v += __shfl_down_sync(0xffffffffu, v, 1, 16);
        if (s16 == 0) uT[(t >> 4) + 16 * it] = v;
    }
    __syncthreads();

    if (t < H_N) {
        const size_t base = (size_t)f * TH;
        const float Xf = X[f];
        float xz = fmaf(xTw[base + t],           Xf, xTb[base + t]);
        float xr = fmaf(xTw[base + H_N + t],     Xf, xTb[base + H_N + t]);
        float xh = fmaf(xTw[base + 2 * H_N + t], Xf, xTb[base + 2 * H_N + t]);

        float z  = 1.0f / (1.0f + expf(-(xz + uT[t])));
        float r  = 1.0f / (1.0f + expf(-(xr + uT[H_N + t])));
        float ht = tanh_acc(fmaf(r, uT[2 * H_N + t], xh));
        float hg = z * Ht_s[t] + (1.0f - z) * ht;   // match reference form

        float oh;
        if (g_count > 0) oh = (mask[f] != 0) ? hg : 0.0f;
        else             oh = Ht_s[t];              // jnp.any(mask) == False

        // out layout: [pred(2), H_curr(F*H)]
        out[2 + (size_t)f * H_N + t] = oh;
    }
}

// ---------------------------------------------------------------------------
// k2: agg[h] = sum_f mask[f] * H_curr[f][h]  (== sum(h_gate*mask) in all
//     branches). H_curr (4MB) is L2-resident after k1. Double atomics keep
//     the accumulation order-insensitive at float32 output precision.
// ---------------------------------------------------------------------------
__global__ void k2_agg(const int* __restrict__ mask,
                       const float* __restrict__ out) {
    __shared__ double s[256];
    const int t = threadIdx.x;
    const int h  = t & 63;
    const int fl = t >> 6;              // 0..3
    const int base = blockIdx.x * 128;  // 128 features per block

    double acc = 0.0;
    #pragma unroll 4
    for (int i = 0; i < 32; i++) {
        int f = base + fl + 4 * i;
        if (mask[f] != 0)
            acc += (double)out[2 + (size_t)f * H_N + h];
    }
    s[t] = acc;
    __syncthreads();
    if (t < 64) {
        double v = s[t] + s[t + 64] + s[t + 128] + s[t + 192];
        atomicAdd(&g_agg[t], v);
    }
}

// ---------------------------------------------------------------------------
// k3: tiny MLP head + 2-class softmax. 256 threads, FLOAT math (double here
//     cost 19.6us measured: software double-exp + serial DFMA on one block).
//     Split-K over W1: quarter q of threads handles h in [16q,16q+16).
// ---------------------------------------------------------------------------
__global__ void k3_mlp(const float* __restrict__ W1, const float* __restrict__ b1,
                       const float* __restrict__ W2, const float* __restrict__ b2,
                       float* __restrict__ out) {
    __shared__ float s_agg[H_N];
    __shared__ float s_part[4][H_N];
    __shared__ float s_hid[H_N];
    __shared__ float s_log[2];
    const int t = threadIdx.x;
    const int n = t & 63;       // output neuron
    const int q = t >> 6;       // 0..3, k-split quarter

    if (t < H_N) {
        const float denom = fmaxf((float)g_count, 1.0f);
        s_agg[t] = (float)g_agg[t] / denom;
    }
    __syncthreads();

    {
        float a = (q == 0) ? b1[n] : 0.0f;
        #pragma unroll
        for (int j = 0; j < 16; j++) {
            int h = q * 16 + j;
            a = fmaf(s_agg[h], W1[h * H_N + n], a);
        }
        s_part[q][n] = a;
    }
    __syncthreads();

    if (t < H_N) {
        float a = s_part[0][t] + s_part[1][t] + s_part[2][t] + s_part[3][t];
        s_hid[t] = fmaxf(a, 0.0f);
    }
    __syncthreads();

    if (t < 2) {
        float a = b2[t];
        #pragma unroll 8
        for (int j = 0; j < H_N; j++) a = fmaf(s_hid[j], W2[j * 2 + t], a);
        s_log[t] = a;
    }
    __syncthreads();

    if (t < 2) {
        float m  = fmaxf(s_log[0], s_log[1]);
        float e0 = expf(s_log[0] - m);
        float e1 = expf(s_log[1] - m);
        out[t] = ((t == 0) ? e0 : e1) / (e0 + e1);
    }
}

// ---------------------------------------------------------------------------
// Inputs (metadata order): 0:tim(i32) 1:X 2:X_hap 3:mask(i32) 4:Ht 5:xT_w
//                          6:xT_b 7:U_w 8:W1 9:b1 10:W2 11:b2
// Output: [pred(2), H_curr(16384*64)] float32
// ---------------------------------------------------------------------------
extern "C" void kernel_launch(void* const* d_in, const int* in_sizes, int n_in,
                              void* d_out, int out_size) {
    const float* X    = (const float*)d_in[1];
    const int*   mask = (const int*)d_in[3];
    const float* Ht   = (const float*)d_in[4];
    const float* xTw  = (const float*)d_in[5];
    const float* xTb  = (const float*)d_in[6];
    const float* Uw   = (const float*)d_in[7];
    const float* W1   = (const float*)d_in[8];
    const float* b1   = (const float*)d_in[9];
    const float* W2   = (const float*)d_in[10];
    const float* b2   = (const float*)d_in[11];
    float* out = (float*)d_out;

    k0_mask<<<1, 256>>>(mask);
    k1_gru<<<F_N, 256>>>(X, mask, Ht, xTw, xTb, Uw, out);
    k2_agg<<<F_N / 128, 256>>>(mask, out);
    k3_mlp<<<1, 256>>>(W1, b1, W2, b2, out);
}